// round 8
// baseline (speedup 1.0000x reference)
#include <cuda_runtime.h>
#include <math.h>

#define BATCH 128
#define SEQ   4096
#define SD    5
#define HID   32
#define DIN   9
#define NTOK  (BATCH*SEQ)
#define TPB   128
#define TOKS_PER_BLOCK (TPB*2)   // 256

__device__ float g_temp[NTOK];

typedef unsigned long long ull;

__device__ __forceinline__ ull pk(float lo, float hi) {
    ull r; asm("mov.b64 %0, {%1, %2};" : "=l"(r) : "f"(lo), "f"(hi)); return r;
}
__device__ __forceinline__ void upk(float& lo, float& hi, ull v) {
    asm("mov.b64 {%0, %1}, %2;" : "=f"(lo), "=f"(hi) : "l"(v));
}
__device__ __forceinline__ void ffma2(ull& d, ull a, ull b) {
    asm("fma.rn.f32x2 %0, %1, %2, %0;" : "+l"(d) : "l"(a), "l"(b));
}
__device__ __forceinline__ ull dup(float x) { return pk(x, x); }

__device__ __forceinline__ float tanh_apx(float x) {
    float y; asm("tanh.approx.f32 %0, %1;" : "=f"(y) : "f"(x)); return y;
}

// -------------------------------------------------------------------------
// Kernel 1: per-batch-row inclusive cumsum of delta_x[..., 2] + init temp
// -------------------------------------------------------------------------
__global__ __launch_bounds__(1024) void cumsum_kernel(const float* __restrict__ dx) {
    __shared__ float wsum[32];
    const int b    = blockIdx.x;
    const int tid  = threadIdx.x;
    const int lane = tid & 31;
    const int wid  = tid >> 5;
    const float* row = dx + (size_t)b * SEQ * 6;

    const int s0 = tid * 4;
    float v0 = row[(s0 + 0) * 6 + 2];
    float v1 = row[(s0 + 1) * 6 + 2];
    float v2 = row[(s0 + 2) * 6 + 2];
    float v3 = row[(s0 + 3) * 6 + 2];
    float p0 = v0, p1 = p0 + v1, p2 = p1 + v2, p3 = p2 + v3;
    float tot = p3;

    float s = tot;
    #pragma unroll
    for (int off = 1; off < 32; off <<= 1) {
        float n = __shfl_up_sync(0xffffffffu, s, off);
        if (lane >= off) s += n;
    }
    if (lane == 31) wsum[wid] = s;
    __syncthreads();
    if (wid == 0) {
        float w = wsum[lane];
        #pragma unroll
        for (int off = 1; off < 32; off <<= 1) {
            float n = __shfl_up_sync(0xffffffffu, w, off);
            if (lane >= off) w += n;
        }
        wsum[lane] = w;
    }
    __syncthreads();

    float base = row[5] + (s - tot) + ((wid > 0) ? wsum[wid - 1] : 0.0f);
    float* outp = g_temp + (size_t)b * SEQ + s0;
    outp[0] = base + p0; outp[1] = base + p1;
    outp[2] = base + p2; outp[3] = base + p3;
}

// -------------------------------------------------------------------------
// Kernel 2: 2 tokens/thread, gate-packed f32x2 accumulators.
// Weight pair (wa,wb) feeds FMAs straight from LDS.64 -- no dup movs.
// -------------------------------------------------------------------------
__global__ __launch_bounds__(TPB, 2) void msc_main(
    const float* __restrict__ h_prev,  const float* __restrict__ delta_x,
    const float* __restrict__ Wa0,     const float* __restrict__ ba0,
    const float* __restrict__ Wb0,     const float* __restrict__ bb0,
    const float* __restrict__ Wa1,     const float* __restrict__ ba1,
    const float* __restrict__ Wb1,     const float* __restrict__ bb1,
    const float* __restrict__ W_alpha, const float* __restrict__ b_alpha,
    const float* __restrict__ W_beta,  const float* __restrict__ b_beta,
    const float* __restrict__ W_gamma, const float* __restrict__ b_gamma,
    const float* __restrict__ W_c,     const float* __restrict__ b_c,
    const float* __restrict__ W_out,
    float* __restrict__ out)
{
    __shared__ ull  sW0[DIN * HID];      // (Wa0, Wb0) pairs, [i*HID + j]
    __shared__ ull  sW1[HID * HID];      // (Wa1, Wb1) pairs
    __shared__ ull  sB0[HID];            // (ba0[j], bb0[j])
    __shared__ ull  sB1[HID];            // (ba1[j], bb1[j])
    __shared__ ull  sH[HID][4];          // head weight pairs per j
    __shared__ ull  sAinit[4];
    __shared__ float sWout[SD];

    const int tid = threadIdx.x;

    for (int idx = tid; idx < HID * HID; idx += TPB)
        sW1[idx] = pk(Wa1[idx], Wb1[idx]);
    for (int idx = tid; idx < DIN * HID; idx += TPB)
        sW0[idx] = pk(Wa0[idx], Wb0[idx]);
    if (tid < HID) {
        sB0[tid] = pk(ba0[tid], bb0[tid]);
        sB1[tid] = pk(ba1[tid], bb1[tid]);
        sH[tid][0] = pk(W_alpha[tid],       W_beta[tid]);
        sH[tid][1] = pk(W_gamma[tid],       W_c[tid * SD + 0]);
        sH[tid][2] = pk(W_c[tid * SD + 1],  W_c[tid * SD + 2]);
        sH[tid][3] = pk(W_c[tid * SD + 3],  W_c[tid * SD + 4]);
    }
    if (tid == 0) {
        sAinit[0] = pk(b_alpha[0], b_beta[0]);
        sAinit[1] = pk(b_gamma[0], b_c[0]);
        sAinit[2] = pk(b_c[1],     b_c[2]);
        sAinit[3] = pk(b_c[3],     b_c[4]);
    }
    if (tid < SD) sWout[tid] = W_out[tid];
    __syncthreads();

    const int t0 = blockIdx.x * TOKS_PER_BLOCK + tid;   // tokens t0, t0+TPB

    // ---- per-token inputs, duplicated-packed for gate-packed FMAs ----
    ull l0d[DIN], l1d[DIN];
    #pragma unroll
    for (int k = 0; k < 2; k++) {
        const int t = t0 + k * TPB;
        const float* hp = h_prev  + (size_t)t * SD;
        const float* dx = delta_x + (size_t)t * 6;
        float lv[DIN];
        #pragma unroll
        for (int d = 0; d < SD; d++) lv[d] = hp[d];
        float d0 = dx[0], d1 = dx[1], d2 = dx[2];
        float nrm = sqrtf(fmaf(d0, d0, fmaf(d1, d1, d2 * d2)));
        nrm = fmaxf(nrm, 1e-7f);
        float inv = __fdividef(1.0f, nrm);
        lv[5] = g_temp[t];
        lv[6] = d0 * inv; lv[7] = d1 * inv; lv[8] = d2 * inv;
        #pragma unroll
        for (int d = 0; d < DIN; d++) {
            if (k == 0) l0d[d] = dup(lv[d]); else l1d[d] = dup(lv[d]);
        }
    }

    // ---------------- layer 0: 9 -> 32 gated ----------------
    // accumulator A_t = (a_gate, b_gate); weight operand = smem pair as-is
    ull u0d[HID], u1d[HID];   // dup-packed activations for layer 1
    #pragma unroll 2
    for (int j = 0; j < HID; j++) {
        ull A0 = sB0[j];
        ull A1 = A0;
        #pragma unroll
        for (int i = 0; i < DIN; i++) {
            ull w = sW0[i * HID + j];
            ffma2(A0, l0d[i], w);
            ffma2(A1, l1d[i], w);
        }
        float a, b;
        upk(a, b, A0); u0d[j] = dup(tanh_apx(a) * tanh_apx(b));
        upk(a, b, A1); u1d[j] = dup(tanh_apx(a) * tanh_apx(b));
    }

    // ---------------- layer 1 (32->32 gated) fused with heads -----------
    ull H0_0 = sAinit[0], H0_1 = H0_0;   // (alpha, beta) per token
    ull H1_0 = sAinit[1], H1_1 = H1_0;   // (gamma, c0)
    ull H2_0 = sAinit[2], H2_1 = H2_0;   // (c1, c2)
    ull H3_0 = sAinit[3], H3_1 = H3_0;   // (c3, c4)

    #pragma unroll 2
    for (int j = 0; j < HID; j++) {
        ull A0 = sB1[j];
        ull A1 = A0;
        #pragma unroll
        for (int i = 0; i < HID; i++) {
            ull w = sW1[i * HID + j];
            ffma2(A0, u0d[i], w);
            ffma2(A1, u1d[i], w);
        }
        float a, b;
        upk(a, b, A0); float v0 = tanh_apx(a) * tanh_apx(b);
        upk(a, b, A1); float v1 = tanh_apx(a) * tanh_apx(b);

        ull hw0 = sH[j][0], hw1 = sH[j][1], hw2 = sH[j][2], hw3 = sH[j][3];
        ull vd0 = dup(v0), vd1 = dup(v1);
        ffma2(H0_0, vd0, hw0); ffma2(H1_0, vd0, hw1);
        ffma2(H2_0, vd0, hw2); ffma2(H3_0, vd0, hw3);
        ffma2(H0_1, vd1, hw0); ffma2(H1_1, vd1, hw1);
        ffma2(H2_1, vd1, hw2); ffma2(H3_1, vd1, hw3);
    }

    // ---------------- tail: per-token heads, gate, outputs ---------------
    ull H0k[2] = { H0_0, H0_1 };
    ull H1k[2] = { H1_0, H1_1 };
    ull H2k[2] = { H2_0, H2_1 };
    ull H3k[2] = { H3_0, H3_1 };

    #pragma unroll
    for (int k = 0; k < 2; k++) {
        const int t = t0 + k * TPB;
        const float* dx = delta_x + (size_t)t * 6;
        const float* hp = h_prev  + (size_t)t * SD;

        float sa, sb, sg, c0, c1, c2, c3, c4;
        upk(sa, sb, H0k[k]);
        upk(sg, c0, H1k[k]);
        upk(c1, c2, H2k[k]);
        upk(c3, c4, H3k[k]);

        const float alpha = __expf(sa);
        const float beta  = __expf(sb);
        const float gamma = __expf(sg);

        const float d0 = dx[0], d1 = dx[1], d2 = dx[2];
        const float zarg = fmaf(alpha, fabsf(d0), fmaf(beta, d1, gamma * fabsf(d2)));
        const float z = 1.0f - __expf(-zarg);

        float c[SD] = { c0, c1, c2, c3, c4 };
        float sigma = 0.0f;
        #pragma unroll
        for (int d = 0; d < SD; d++) {
            const float hv = hp[d];
            const float cn = tanh_apx(c[d]);
            const float hn = fmaf(z, cn - hv, hv);
            out[(size_t)t * SD + d] = hn;
            sigma = fmaf(hn, sWout[d], sigma);
        }
        out[(size_t)NTOK * SD + t] = sigma;
    }
}

extern "C" void kernel_launch(void* const* d_in, const int* in_sizes, int n_in,
                              void* d_out, int out_size) {
    const float* h_prev  = (const float*)d_in[0];
    const float* delta_x = (const float*)d_in[1];
    const float* Wa0     = (const float*)d_in[2];
    const float* ba0     = (const float*)d_in[3];
    const float* Wb0     = (const float*)d_in[4];
    const float* bb0     = (const float*)d_in[5];
    const float* Wa1     = (const float*)d_in[6];
    const float* ba1     = (const float*)d_in[7];
    const float* Wb1     = (const float*)d_in[8];
    const float* bb1     = (const float*)d_in[9];
    const float* W_alpha = (const float*)d_in[10];
    const float* b_alpha = (const float*)d_in[11];
    const float* W_beta  = (const float*)d_in[12];
    const float* b_beta  = (const float*)d_in[13];
    const float* W_gamma = (const float*)d_in[14];
    const float* b_gamma = (const float*)d_in[15];
    const float* W_c     = (const float*)d_in[16];
    const float* b_c     = (const float*)d_in[17];
    const float* W_out   = (const float*)d_in[18];
    float* out = (float*)d_out;

    cumsum_kernel<<<BATCH, 1024>>>(delta_x);
    msc_main<<<NTOK / TOKS_PER_BLOCK, TPB>>>(h_prev, delta_x,
                                             Wa0, ba0, Wb0, bb0,
                                             Wa1, ba1, Wb1, bb1,
                                             W_alpha, b_alpha, W_beta, b_beta,
                                             W_gamma, b_gamma, W_c, b_c, W_out,
                                             out);
}

// round 9
// speedup vs baseline: 1.1068x; 1.1068x over previous
#include <cuda_runtime.h>
#include <math.h>

#define BATCH 128
#define SEQ   4096
#define SD    5
#define HID   32
#define DIN   9
#define NTOK  (BATCH*SEQ)
#define TPB   128
#define TOKS_PER_BLOCK (TPB*4)   // 512

__device__ float g_temp[NTOK];

typedef unsigned long long ull;

__device__ __forceinline__ ull pk(float lo, float hi) {
    ull r; asm("mov.b64 %0, {%1, %2};" : "=l"(r) : "f"(lo), "f"(hi)); return r;
}
__device__ __forceinline__ void upk(float& lo, float& hi, ull v) {
    asm("mov.b64 {%0, %1}, %2;" : "=f"(lo), "=f"(hi) : "l"(v));
}
__device__ __forceinline__ void ffma2(ull& d, ull a, ull b) {
    asm("fma.rn.f32x2 %0, %1, %2, %0;" : "+l"(d) : "l"(a), "l"(b));
}
__device__ __forceinline__ ull dup(float x) { return pk(x, x); }

__device__ __forceinline__ float tanh_apx(float x) {
    float y; asm("tanh.approx.f32 %0, %1;" : "=f"(y) : "f"(x)); return y;
}
// pack (lo,hi) f32 -> bf16x2 (lo in low half)
__device__ __forceinline__ unsigned int pk_bf2(float lo, float hi) {
    unsigned int r;
    asm("cvt.rn.bf16x2.f32 %0, %1, %2;" : "=r"(r) : "f"(hi), "f"(lo));
    return r;
}
// expand bf16x2 -> f32x2 pair
__device__ __forceinline__ ull upk_bf2(unsigned int p) {
    unsigned int lo = p << 16;
    unsigned int hi = p & 0xFFFF0000u;
    return pk(__uint_as_float(lo), __uint_as_float(hi));
}

// -------------------------------------------------------------------------
// Kernel 1: per-batch-row inclusive cumsum of delta_x[..., 2] + init temp
// -------------------------------------------------------------------------
__global__ __launch_bounds__(1024) void cumsum_kernel(const float* __restrict__ dx) {
    __shared__ float wsum[32];
    const int b    = blockIdx.x;
    const int tid  = threadIdx.x;
    const int lane = tid & 31;
    const int wid  = tid >> 5;
    const float* row = dx + (size_t)b * SEQ * 6;

    const int s0 = tid * 4;
    float v0 = row[(s0 + 0) * 6 + 2];
    float v1 = row[(s0 + 1) * 6 + 2];
    float v2 = row[(s0 + 2) * 6 + 2];
    float v3 = row[(s0 + 3) * 6 + 2];
    float p0 = v0, p1 = p0 + v1, p2 = p1 + v2, p3 = p2 + v3;
    float tot = p3;

    float s = tot;
    #pragma unroll
    for (int off = 1; off < 32; off <<= 1) {
        float n = __shfl_up_sync(0xffffffffu, s, off);
        if (lane >= off) s += n;
    }
    if (lane == 31) wsum[wid] = s;
    __syncthreads();
    if (wid == 0) {
        float w = wsum[lane];
        #pragma unroll
        for (int off = 1; off < 32; off <<= 1) {
            float n = __shfl_up_sync(0xffffffffu, w, off);
            if (lane >= off) w += n;
        }
        wsum[lane] = w;
    }
    __syncthreads();

    float base = row[5] + (s - tot) + ((wid > 0) ? wsum[wid - 1] : 0.0f);
    float* outp = g_temp + (size_t)b * SEQ + s0;
    outp[0] = base + p0; outp[1] = base + p1;
    outp[2] = base + p2; outp[3] = base + p3;
}

// -------------------------------------------------------------------------
// Kernel 2: 4 tokens/thread (token-packed f32x2), activations held as
// bf16x2 in registers (64 regs), 3 blocks/SM for occupancy.
// -------------------------------------------------------------------------
__global__ __launch_bounds__(TPB, 3) void msc_main(
    const float* __restrict__ h_prev,  const float* __restrict__ delta_x,
    const float* __restrict__ Wa0,     const float* __restrict__ ba0,
    const float* __restrict__ Wb0,     const float* __restrict__ bb0,
    const float* __restrict__ Wa1,     const float* __restrict__ ba1,
    const float* __restrict__ Wb1,     const float* __restrict__ bb1,
    const float* __restrict__ W_alpha, const float* __restrict__ b_alpha,
    const float* __restrict__ W_beta,  const float* __restrict__ b_beta,
    const float* __restrict__ W_gamma, const float* __restrict__ b_gamma,
    const float* __restrict__ W_c,     const float* __restrict__ b_c,
    const float* __restrict__ W_out,
    float* __restrict__ out)
{
    __shared__ ull  sW0[DIN * HID];      // (Wa0, Wb0) pairs, [i*HID + j]
    __shared__ ull  sW1[HID * HID];      // (Wa1, Wb1) pairs
    __shared__ ull  sB0[HID];            // (ba0[j], bb0[j])
    __shared__ ull  sB1[HID];            // (ba1[j], bb1[j])
    __shared__ ull  sH[HID][4];          // head weight pairs per j
    __shared__ ull  sAinit[4];
    __shared__ float sWout[SD];

    const int tid = threadIdx.x;

    for (int idx = tid; idx < HID * HID; idx += TPB)
        sW1[idx] = pk(Wa1[idx], Wb1[idx]);
    for (int idx = tid; idx < DIN * HID; idx += TPB)
        sW0[idx] = pk(Wa0[idx], Wb0[idx]);
    if (tid < HID) {
        sB0[tid] = pk(ba0[tid], bb0[tid]);
        sB1[tid] = pk(ba1[tid], bb1[tid]);
        sH[tid][0] = pk(W_alpha[tid],       W_beta[tid]);
        sH[tid][1] = pk(W_gamma[tid],       W_c[tid * SD + 0]);
        sH[tid][2] = pk(W_c[tid * SD + 1],  W_c[tid * SD + 2]);
        sH[tid][3] = pk(W_c[tid * SD + 3],  W_c[tid * SD + 4]);
    }
    if (tid == 0) {
        sAinit[0] = pk(b_alpha[0], b_beta[0]);
        sAinit[1] = pk(b_gamma[0], b_c[0]);
        sAinit[2] = pk(b_c[1],     b_c[2]);
        sAinit[3] = pk(b_c[3],     b_c[4]);
    }
    if (tid < SD) sWout[tid] = W_out[tid];
    __syncthreads();

    const int t0 = blockIdx.x * TOKS_PER_BLOCK + tid;   // tokens t0 + k*TPB

    // ---- per-token inputs, token-packed f32x2 pairs ----
    ull l01[DIN], l23[DIN];
    {
        float lv[4][DIN];
        #pragma unroll
        for (int k = 0; k < 4; k++) {
            const int t = t0 + k * TPB;
            const float* hp = h_prev  + (size_t)t * SD;
            const float* dx = delta_x + (size_t)t * 6;
            #pragma unroll
            for (int d = 0; d < SD; d++) lv[k][d] = hp[d];
            float d0 = dx[0], d1 = dx[1], d2 = dx[2];
            float nrm = sqrtf(fmaf(d0, d0, fmaf(d1, d1, d2 * d2)));
            nrm = fmaxf(nrm, 1e-7f);
            float inv = __fdividef(1.0f, nrm);
            lv[k][5] = g_temp[t];
            lv[k][6] = d0 * inv; lv[k][7] = d1 * inv; lv[k][8] = d2 * inv;
        }
        #pragma unroll
        for (int d = 0; d < DIN; d++) {
            l01[d] = pk(lv[0][d], lv[1][d]);
            l23[d] = pk(lv[2][d], lv[3][d]);
        }
    }

    // ---------------- layer 0: 9 -> 32 gated, u kept bf16x2 in regs ------
    uint2 uq[HID];    // (bf16x2(u0,u1), bf16x2(u2,u3)) per hidden unit
    #pragma unroll 2
    for (int j = 0; j < HID; j++) {
        ull a01 = sB0[j], a23 = a01, b01 = a01, b23 = a01;
        // note: bias pair is (ba,bb); token-packed accums need (ba,ba)/(bb,bb)
        {
            float ba, bb; upk(ba, bb, sB0[j]);
            a01 = dup(ba); a23 = a01;
            b01 = dup(bb); b23 = b01;
        }
        #pragma unroll
        for (int i = 0; i < DIN; i++) {
            ull w = sW0[i * HID + j];
            float wa, wb; upk(wa, wb, w);
            ull wad = dup(wa), wbd = dup(wb);
            ffma2(a01, l01[i], wad);
            ffma2(a23, l23[i], wad);
            ffma2(b01, l01[i], wbd);
            ffma2(b23, l23[i], wbd);
        }
        float x0, x1, x2, x3, y0, y1, y2, y3;
        upk(x0, x1, a01); upk(x2, x3, a23);
        upk(y0, y1, b01); upk(y2, y3, b23);
        float u0 = tanh_apx(x0) * tanh_apx(y0);
        float u1 = tanh_apx(x1) * tanh_apx(y1);
        float u2 = tanh_apx(x2) * tanh_apx(y2);
        float u3 = tanh_apx(x3) * tanh_apx(y3);
        uq[j] = make_uint2(pk_bf2(u0, u1), pk_bf2(u2, u3));
    }

    // ---------------- layer 1 (32->32 gated) fused with heads ------------
    ull H0_0 = sAinit[0], H0_1 = H0_0, H0_2 = H0_0, H0_3 = H0_0;
    ull H1_0 = sAinit[1], H1_1 = H1_0, H1_2 = H1_0, H1_3 = H1_0;
    ull H2_0 = sAinit[2], H2_1 = H2_0, H2_2 = H2_0, H2_3 = H2_0;
    ull H3_0 = sAinit[3], H3_1 = H3_0, H3_2 = H3_0, H3_3 = H3_0;

    #pragma unroll 1
    for (int jg = 0; jg < HID; jg += 4) {
        ull a01[4], a23[4], b01[4], b23[4];
        #pragma unroll
        for (int m = 0; m < 4; m++) {
            float ba, bb; upk(ba, bb, sB1[jg + m]);
            a01[m] = dup(ba); a23[m] = a01[m];
            b01[m] = dup(bb); b23[m] = b01[m];
        }
        #pragma unroll
        for (int i = 0; i < HID; i++) {
            const uint2 p = uq[i];
            const ull u01 = upk_bf2(p.x);
            const ull u23 = upk_bf2(p.y);
            #pragma unroll
            for (int m = 0; m < 4; m++) {
                ull w = sW1[i * HID + jg + m];
                float wa, wb; upk(wa, wb, w);
                ull wad = dup(wa), wbd = dup(wb);
                ffma2(a01[m], u01, wad);
                ffma2(a23[m], u23, wad);
                ffma2(b01[m], u01, wbd);
                ffma2(b23[m], u23, wbd);
            }
        }
        #pragma unroll
        for (int m = 0; m < 4; m++) {
            const int j = jg + m;
            float x0, x1, x2, x3, y0, y1, y2, y3;
            upk(x0, x1, a01[m]); upk(x2, x3, a23[m]);
            upk(y0, y1, b01[m]); upk(y2, y3, b23[m]);
            float v0 = tanh_apx(x0) * tanh_apx(y0);
            float v1 = tanh_apx(x1) * tanh_apx(y1);
            float v2 = tanh_apx(x2) * tanh_apx(y2);
            float v3 = tanh_apx(x3) * tanh_apx(y3);

            ull hw0 = sH[j][0], hw1 = sH[j][1], hw2 = sH[j][2], hw3 = sH[j][3];
            ull vd;
            vd = dup(v0); ffma2(H0_0, vd, hw0); ffma2(H1_0, vd, hw1);
                          ffma2(H2_0, vd, hw2); ffma2(H3_0, vd, hw3);
            vd = dup(v1); ffma2(H0_1, vd, hw0); ffma2(H1_1, vd, hw1);
                          ffma2(H2_1, vd, hw2); ffma2(H3_1, vd, hw3);
            vd = dup(v2); ffma2(H0_2, vd, hw0); ffma2(H1_2, vd, hw1);
                          ffma2(H2_2, vd, hw2); ffma2(H3_2, vd, hw3);
            vd = dup(v3); ffma2(H0_3, vd, hw0); ffma2(H1_3, vd, hw1);
                          ffma2(H2_3, vd, hw2); ffma2(H3_3, vd, hw3);
        }
    }

    // ---------------- tail: per-token heads, gate, outputs ---------------
    ull H0k[4] = { H0_0, H0_1, H0_2, H0_3 };
    ull H1k[4] = { H1_0, H1_1, H1_2, H1_3 };
    ull H2k[4] = { H2_0, H2_1, H2_2, H2_3 };
    ull H3k[4] = { H3_0, H3_1, H3_2, H3_3 };

    #pragma unroll
    for (int k = 0; k < 4; k++) {
        const int t = t0 + k * TPB;
        const float* dx = delta_x + (size_t)t * 6;
        const float* hp = h_prev  + (size_t)t * SD;

        float sa, sb, sg, c0, c1, c2, c3, c4;
        upk(sa, sb, H0k[k]);
        upk(sg, c0, H1k[k]);
        upk(c1, c2, H2k[k]);
        upk(c3, c4, H3k[k]);

        const float alpha = __expf(sa);
        const float beta  = __expf(sb);
        const float gamma = __expf(sg);

        const float d0 = dx[0], d1 = dx[1], d2 = dx[2];
        const float zarg = fmaf(alpha, fabsf(d0), fmaf(beta, d1, gamma * fabsf(d2)));
        const float z = 1.0f - __expf(-zarg);

        float c[SD] = { c0, c1, c2, c3, c4 };
        float sigma = 0.0f;
        #pragma unroll
        for (int d = 0; d < SD; d++) {
            const float hv = hp[d];
            const float cn = tanh_apx(c[d]);
            const float hn = fmaf(z, cn - hv, hv);
            out[(size_t)t * SD + d] = hn;
            sigma = fmaf(hn, sWout[d], sigma);
        }
        out[(size_t)NTOK * SD + t] = sigma;
    }
}

extern "C" void kernel_launch(void* const* d_in, const int* in_sizes, int n_in,
                              void* d_out, int out_size) {
    const float* h_prev  = (const float*)d_in[0];
    const float* delta_x = (const float*)d_in[1];
    const float* Wa0     = (const float*)d_in[2];
    const float* ba0     = (const float*)d_in[3];
    const float* Wb0     = (const float*)d_in[4];
    const float* bb0     = (const float*)d_in[5];
    const float* Wa1     = (const float*)d_in[6];
    const float* ba1     = (const float*)d_in[7];
    const float* Wb1     = (const float*)d_in[8];
    const float* bb1     = (const float*)d_in[9];
    const float* W_alpha = (const float*)d_in[10];
    const float* b_alpha = (const float*)d_in[11];
    const float* W_beta  = (const float*)d_in[12];
    const float* b_beta  = (const float*)d_in[13];
    const float* W_gamma = (const float*)d_in[14];
    const float* b_gamma = (const float*)d_in[15];
    const float* W_c     = (const float*)d_in[16];
    const float* b_c     = (const float*)d_in[17];
    const float* W_out   = (const float*)d_in[18];
    float* out = (float*)d_out;

    cumsum_kernel<<<BATCH, 1024>>>(delta_x);
    msc_main<<<NTOK / TOKS_PER_BLOCK, TPB>>>(h_prev, delta_x,
                                             Wa0, ba0, Wb0, bb0,
                                             Wa1, ba1, Wb1, bb1,
                                             W_alpha, b_alpha, W_beta, b_beta,
                                             W_gamma, b_gamma, W_c, b_c, W_out,
                                             out);
}

// round 13
// speedup vs baseline: 1.3899x; 1.2558x over previous
#include <cuda_runtime.h>
#include <math.h>

#define BATCH 128
#define SEQ   4096
#define SD    5
#define HID   32
#define DIN   9
#define NTOK  (BATCH*SEQ)
#define TPB   128
#define TOKS_PER_BLOCK (TPB*4)   // 512

__device__ float g_temp[NTOK];

typedef unsigned long long ull;

__device__ __forceinline__ ull pk(float lo, float hi) {
    ull r; asm("mov.b64 %0, {%1, %2};" : "=l"(r) : "f"(lo), "f"(hi)); return r;
}
__device__ __forceinline__ void upk(float& lo, float& hi, ull v) {
    asm("mov.b64 {%0, %1}, %2;" : "=f"(lo), "=f"(hi) : "l"(v));
}
__device__ __forceinline__ void ffma2(ull& d, ull a, ull b) {
    asm("fma.rn.f32x2 %0, %1, %2, %0;" : "+l"(d) : "l"(a), "l"(b));
}
__device__ __forceinline__ ull dup(float x) { return pk(x, x); }

__device__ __forceinline__ float tanh_apx(float x) {
    float y; asm("tanh.approx.f32 %0, %1;" : "=f"(y) : "f"(x)); return y;
}

// -------------------------------------------------------------------------
// Kernel 1: per-batch-row inclusive cumsum of delta_x[..., 2] + init temp
// -------------------------------------------------------------------------
__global__ __launch_bounds__(1024) void cumsum_kernel(const float* __restrict__ dx) {
    __shared__ float wsum[32];
    const int b    = blockIdx.x;
    const int tid  = threadIdx.x;
    const int lane = tid & 31;
    const int wid  = tid >> 5;
    const float* row = dx + (size_t)b * SEQ * 6;

    const int s0 = tid * 4;
    float v0 = row[(s0 + 0) * 6 + 2];
    float v1 = row[(s0 + 1) * 6 + 2];
    float v2 = row[(s0 + 2) * 6 + 2];
    float v3 = row[(s0 + 3) * 6 + 2];
    float p0 = v0, p1 = p0 + v1, p2 = p1 + v2, p3 = p2 + v3;
    float tot = p3;

    float s = tot;
    #pragma unroll
    for (int off = 1; off < 32; off <<= 1) {
        float n = __shfl_up_sync(0xffffffffu, s, off);
        if (lane >= off) s += n;
    }
    if (lane == 31) wsum[wid] = s;
    __syncthreads();
    if (wid == 0) {
        float w = wsum[lane];
        #pragma unroll
        for (int off = 1; off < 32; off <<= 1) {
            float n = __shfl_up_sync(0xffffffffu, w, off);
            if (lane >= off) w += n;
        }
        wsum[lane] = w;
    }
    __syncthreads();

    float base = row[5] + (s - tot) + ((wid > 0) ? wsum[wid - 1] : 0.0f);
    float* outp = g_temp + (size_t)b * SEQ + s0;
    outp[0] = base + p0; outp[1] = base + p1;
    outp[2] = base + p2; outp[3] = base + p3;
}

// -------------------------------------------------------------------------
// Kernel 2: 4 tokens/thread (token-packed f32x2).
// Weights pre-duplicated in smem as ulonglong2 ((wa,wa),(wb,wb)) so one
// LDS.128 feeds 4 FFMA2 with zero dup-MOVs. u stays in registers (f32x2).
// -------------------------------------------------------------------------
__global__ __launch_bounds__(TPB, 2) void msc_main(
    const float* __restrict__ h_prev,  const float* __restrict__ delta_x,
    const float* __restrict__ Wa0,     const float* __restrict__ ba0,
    const float* __restrict__ Wb0,     const float* __restrict__ bb0,
    const float* __restrict__ Wa1,     const float* __restrict__ ba1,
    const float* __restrict__ Wb1,     const float* __restrict__ bb1,
    const float* __restrict__ W_alpha, const float* __restrict__ b_alpha,
    const float* __restrict__ W_beta,  const float* __restrict__ b_beta,
    const float* __restrict__ W_gamma, const float* __restrict__ b_gamma,
    const float* __restrict__ W_c,     const float* __restrict__ b_c,
    const float* __restrict__ W_out,
    float* __restrict__ out)
{
    __shared__ ulonglong2 sW0[DIN * HID];   // ((wa,wa),(wb,wb))  4.6 KB
    __shared__ ulonglong2 sW1[HID * HID];   // 16 KB
    __shared__ ulonglong2 sB0[HID];         // ((ba,ba),(bb,bb))
    __shared__ ulonglong2 sB1[HID];
    __shared__ ull  sH[HID][4];             // head weight pairs per j
    __shared__ ull  sAinit[4];
    __shared__ float sWout[SD];

    const int tid = threadIdx.x;

    for (int idx = tid; idx < HID * HID; idx += TPB) {
        float wa = Wa1[idx], wb = Wb1[idx];
        sW1[idx] = make_ulonglong2(pk(wa, wa), pk(wb, wb));
    }
    for (int idx = tid; idx < DIN * HID; idx += TPB) {
        float wa = Wa0[idx], wb = Wb0[idx];
        sW0[idx] = make_ulonglong2(pk(wa, wa), pk(wb, wb));
    }
    if (tid < HID) {
        sB0[tid] = make_ulonglong2(dup(ba0[tid]), dup(bb0[tid]));
        sB1[tid] = make_ulonglong2(dup(ba1[tid]), dup(bb1[tid]));
        sH[tid][0] = pk(W_alpha[tid],       W_beta[tid]);
        sH[tid][1] = pk(W_gamma[tid],       W_c[tid * SD + 0]);
        sH[tid][2] = pk(W_c[tid * SD + 1],  W_c[tid * SD + 2]);
        sH[tid][3] = pk(W_c[tid * SD + 3],  W_c[tid * SD + 4]);
    }
    if (tid == 0) {
        sAinit[0] = pk(b_alpha[0], b_beta[0]);
        sAinit[1] = pk(b_gamma[0], b_c[0]);
        sAinit[2] = pk(b_c[1],     b_c[2]);
        sAinit[3] = pk(b_c[3],     b_c[4]);
    }
    if (tid < SD) sWout[tid] = W_out[tid];
    __syncthreads();

    const int t0 = blockIdx.x * TOKS_PER_BLOCK + tid;   // tokens t0 + k*TPB

    // ---- per-token inputs, token-packed f32x2 pairs ----
    ull l01[DIN], l23[DIN];
    {
        float lv[4][DIN];
        #pragma unroll
        for (int k = 0; k < 4; k++) {
            const int t = t0 + k * TPB;
            const float* hp = h_prev  + (size_t)t * SD;
            const float* dxp = delta_x + (size_t)t * 6;
            #pragma unroll
            for (int d = 0; d < SD; d++) lv[k][d] = hp[d];
            float d0 = dxp[0], d1 = dxp[1], d2 = dxp[2];
            float nrm = sqrtf(fmaf(d0, d0, fmaf(d1, d1, d2 * d2)));
            nrm = fmaxf(nrm, 1e-7f);
            float inv = __fdividef(1.0f, nrm);
            lv[k][5] = g_temp[t];
            lv[k][6] = d0 * inv; lv[k][7] = d1 * inv; lv[k][8] = d2 * inv;
        }
        #pragma unroll
        for (int d = 0; d < DIN; d++) {
            l01[d] = pk(lv[0][d], lv[1][d]);
            l23[d] = pk(lv[2][d], lv[3][d]);
        }
    }

    // ---------------- layer 0: 9 -> 32 gated, u in f32x2 registers --------
    ull u01[HID], u23[HID];
    #pragma unroll 2
    for (int j = 0; j < HID; j++) {
        ulonglong2 bb = sB0[j];
        ull a01 = bb.x, a23 = bb.x;   // a-gate accums (tok01, tok23)
        ull g01 = bb.y, g23 = bb.y;   // b-gate accums
        #pragma unroll
        for (int i = 0; i < DIN; i++) {
            ulonglong2 w = sW0[i * HID + j];
            ffma2(a01, l01[i], w.x);
            ffma2(a23, l23[i], w.x);
            ffma2(g01, l01[i], w.y);
            ffma2(g23, l23[i], w.y);
        }
        float x0, x1, x2, x3, y0, y1, y2, y3;
        upk(x0, x1, a01); upk(x2, x3, a23);
        upk(y0, y1, g01); upk(y2, y3, g23);
        u01[j] = pk(tanh_apx(x0) * tanh_apx(y0), tanh_apx(x1) * tanh_apx(y1));
        u23[j] = pk(tanh_apx(x2) * tanh_apx(y2), tanh_apx(x3) * tanh_apx(y3));
    }

    // ---------------- layer 1 (32->32 gated) fused with heads -------------
    ull H0_0 = sAinit[0], H0_1 = H0_0, H0_2 = H0_0, H0_3 = H0_0;
    ull H1_0 = sAinit[1], H1_1 = H1_0, H1_2 = H1_0, H1_3 = H1_0;
    ull H2_0 = sAinit[2], H2_1 = H2_0, H2_2 = H2_0, H2_3 = H2_0;
    ull H3_0 = sAinit[3], H3_1 = H3_0, H3_2 = H3_0, H3_3 = H3_0;

    #pragma unroll 2
    for (int j = 0; j < HID; j++) {
        ulonglong2 bb = sB1[j];
        ull a01 = bb.x, a23 = bb.x;
        ull g01 = bb.y, g23 = bb.y;
        #pragma unroll
        for (int i = 0; i < HID; i++) {
            ulonglong2 w = sW1[i * HID + j];
            ffma2(a01, u01[i], w.x);
            ffma2(a23, u23[i], w.x);
            ffma2(g01, u01[i], w.y);
            ffma2(g23, u23[i], w.y);
        }
        float x0, x1, x2, x3, y0, y1, y2, y3;
        upk(x0, x1, a01); upk(x2, x3, a23);
        upk(y0, y1, g01); upk(y2, y3, g23);
        float v0 = tanh_apx(x0) * tanh_apx(y0);
        float v1 = tanh_apx(x1) * tanh_apx(y1);
        float v2 = tanh_apx(x2) * tanh_apx(y2);
        float v3 = tanh_apx(x3) * tanh_apx(y3);

        ull hw0 = sH[j][0], hw1 = sH[j][1], hw2 = sH[j][2], hw3 = sH[j][3];
        ull vd;
        vd = dup(v0); ffma2(H0_0, vd, hw0); ffma2(H1_0, vd, hw1);
                      ffma2(H2_0, vd, hw2); ffma2(H3_0, vd, hw3);
        vd = dup(v1); ffma2(H0_1, vd, hw0); ffma2(H1_1, vd, hw1);
                      ffma2(H2_1, vd, hw2); ffma2(H3_1, vd, hw3);
        vd = dup(v2); ffma2(H0_2, vd, hw0); ffma2(H1_2, vd, hw1);
                      ffma2(H2_2, vd, hw2); ffma2(H3_2, vd, hw3);
        vd = dup(v3); ffma2(H0_3, vd, hw0); ffma2(H1_3, vd, hw1);
                      ffma2(H2_3, vd, hw2); ffma2(H3_3, vd, hw3);
    }

    // ---------------- tail: per-token heads, gate, outputs ----------------
    ull H0k[4] = { H0_0, H0_1, H0_2, H0_3 };
    ull H1k[4] = { H1_0, H1_1, H1_2, H1_3 };
    ull H2k[4] = { H2_0, H2_1, H2_2, H2_3 };
    ull H3k[4] = { H3_0, H3_1, H3_2, H3_3 };

    #pragma unroll
    for (int k = 0; k < 4; k++) {
        const int t = t0 + k * TPB;
        const float* dxp = delta_x + (size_t)t * 6;
        const float* hp = h_prev  + (size_t)t * SD;

        float sa, sb, sg, c0, c1, c2, c3, c4;
        upk(sa, sb, H0k[k]);
        upk(sg, c0, H1k[k]);
        upk(c1, c2, H2k[k]);
        upk(c3, c4, H3k[k]);

        const float alpha = __expf(sa);
        const float beta  = __expf(sb);
        const float gamma = __expf(sg);

        const float d0 = dxp[0], d1 = dxp[1], d2 = dxp[2];
        const float zarg = fmaf(alpha, fabsf(d0), fmaf(beta, d1, gamma * fabsf(d2)));
        const float z = 1.0f - __expf(-zarg);

        float c[SD] = { c0, c1, c2, c3, c4 };
        float sigma = 0.0f;
        #pragma unroll
        for (int d = 0; d < SD; d++) {
            const float hv = hp[d];
            const float cn = tanh_apx(c[d]);
            const float hn = fmaf(z, cn - hv, hv);
            out[(size_t)t * SD + d] = hn;
            sigma = fmaf(hn, sWout[d], sigma);
        }
        out[(size_t)NTOK * SD + t] = sigma;
    }
}

extern "C" void kernel_launch(void* const* d_in, const int* in_sizes, int n_in,
                              void* d_out, int out_size) {
    const float* h_prev  = (const float*)d_in[0];
    const float* delta_x = (const float*)d_in[1];
    const float* Wa0     = (const float*)d_in[2];
    const float* ba0     = (const float*)d_in[3];
    const float* Wb0     = (const float*)d_in[4];
    const float* bb0     = (const float*)d_in[5];
    const float* Wa1     = (const float*)d_in[6];
    const float* ba1     = (const float*)d_in[7];
    const float* Wb1     = (const float*)d_in[8];
    const float* bb1     = (const float*)d_in[9];
    const float* W_alpha = (const float*)d_in[10];
    const float* b_alpha = (const float*)d_in[11];
    const float* W_beta  = (const float*)d_in[12];
    const float* b_beta  = (const float*)d_in[13];
    const float* W_gamma = (const float*)d_in[14];
    const float* b_gamma = (const float*)d_in[15];
    const float* W_c     = (const float*)d_in[16];
    const float* b_c     = (const float*)d_in[17];
    const float* W_out   = (const float*)d_in[18];
    float* out = (float*)d_out;

    cumsum_kernel<<<BATCH, 1024>>>(delta_x);
    msc_main<<<NTOK / TOKS_PER_BLOCK, TPB>>>(h_prev, delta_x,
                                             Wa0, ba0, Wb0, bb0,
                                             Wa1, ba1, Wb1, bb1,
                                             W_alpha, b_alpha, W_beta, b_beta,
                                             W_gamma, b_gamma, W_c, b_c, W_out,
                                             out);
}